// round 1
// baseline (speedup 1.0000x reference)
#include <cuda_runtime.h>
#include <cstdint>

#define N_MAX   100000
#define E_MAX   1600000
#define IN_F    16

// ---------------- scratch (device globals; no dynamic allocation) ----------------
__device__ float g_ze1[E_MAX * IN_F];
__device__ float g_ze2[E_MAX * IN_F];
__device__ float g_zet[E_MAX * IN_F];
__device__ float g_ze4[E_MAX * IN_F];
__device__ float g_xyagg[E_MAX * IN_F];

__device__ float g_zn1[N_MAX * IN_F];
__device__ float g_zn2[N_MAX * IN_F];
__device__ float g_znt[N_MAX * IN_F];
__device__ float g_zn4[N_MAX * IN_F];
__device__ float g_yx[N_MAX * IN_F];

__device__ float g_stats[64];  // [0:16] sum_x [16:32] sumsq_x [32:48] sum_y [48:64] sumsq_y
__device__ float g_bn[64];     // [0:16] scale_x [16:32] shift_x [32:48] scale_y [48:64] shift_y

// ---------------- helpers ----------------
#define RED4(p, v)                                                              \
    asm volatile("red.global.add.v4.f32 [%0], {%1, %2, %3, %4};"                \
                 :: "l"(p), "f"((v).x), "f"((v).y), "f"((v).z), "f"((v).w)      \
                 : "memory")

static inline unsigned cdiv_u(long long a, long long b) { return (unsigned)((a + b - 1) / b); }

// ---------------- zero-init ----------------
__global__ void zero_all(int e4, int n4) {
    long long i = (long long)blockIdx.x * blockDim.x + threadIdx.x;
    float4 z = make_float4(0.f, 0.f, 0.f, 0.f);
    if (i < e4) {
        ((float4*)g_ze1)[i] = z;
        ((float4*)g_ze2)[i] = z;
        ((float4*)g_zet)[i] = z;
        ((float4*)g_ze4)[i] = z;
        ((float4*)g_xyagg)[i] = z;
    }
    if (i < n4) {
        ((float4*)g_zn1)[i] = z;
        ((float4*)g_zn2)[i] = z;
        ((float4*)g_znt)[i] = z;
        ((float4*)g_zn4)[i] = z;
        ((float4*)g_yx)[i] = z;
    }
    if (i < 16) ((float4*)g_stats)[i] = z;
}

// ---------------- spmm: out[dst[e]] += z[src[e]] ----------------
__global__ void __launch_bounds__(256) spmm16(
    const float* __restrict__ z, const int* __restrict__ src,
    const int* __restrict__ dst, float* __restrict__ out, int nE)
{
    int e = blockIdx.x * blockDim.x + threadIdx.x;
    if (e >= nE) return;
    size_t s4 = (size_t)__ldg(src + e) * 4;
    size_t d4 = (size_t)__ldg(dst + e) * 4;
    const float4* zp = (const float4*)z + s4;
    float4 a0 = __ldg(zp + 0), a1 = __ldg(zp + 1), a2 = __ldg(zp + 2), a3 = __ldg(zp + 3);
    float4* op = (float4*)out + d4;
    RED4(op + 0, a0); RED4(op + 1, a1); RED4(op + 2, a2); RED4(op + 3, a3);
}

// fused first line-graph pass: ze1[d] += y[s];  xyagg[d] += x[eid2nid[s]]
__global__ void __launch_bounds__(256) lg_pass1(
    const float* __restrict__ y, const float* __restrict__ x,
    const int* __restrict__ src, const int* __restrict__ dst,
    const int* __restrict__ e2n,
    float* __restrict__ ze1, float* __restrict__ xyagg, int nE)
{
    int e = blockIdx.x * blockDim.x + threadIdx.x;
    if (e >= nE) return;
    int s = __ldg(src + e);
    size_t d4 = (size_t)__ldg(dst + e) * 4;
    const float4* yp = (const float4*)y + (size_t)s * 4;
    float4 a0 = __ldg(yp + 0), a1 = __ldg(yp + 1), a2 = __ldg(yp + 2), a3 = __ldg(yp + 3);
    float4* op = (float4*)ze1 + d4;
    RED4(op + 0, a0); RED4(op + 1, a1); RED4(op + 2, a2); RED4(op + 3, a3);
    int nid = __ldg(e2n + s);
    const float4* xp = (const float4*)x + (size_t)nid * 4;
    float4 b0 = __ldg(xp + 0), b1 = __ldg(xp + 1), b2 = __ldg(xp + 2), b3 = __ldg(xp + 3);
    float4* op2 = (float4*)xyagg + d4;
    RED4(op2 + 0, b0); RED4(op2 + 1, b1); RED4(op2 + 2, b2); RED4(op2 + 3, b3);
}

// yx[dst_g[e]] += y[e]
__global__ void __launch_bounds__(256) yx_kernel(
    const float* __restrict__ y, const int* __restrict__ dst,
    float* __restrict__ out, int nE)
{
    int e = blockIdx.x * blockDim.x + threadIdx.x;
    if (e >= nE) return;
    const float4* yp = (const float4*)y + (size_t)e * 4;
    float4 a0 = __ldg(yp + 0), a1 = __ldg(yp + 1), a2 = __ldg(yp + 2), a3 = __ldg(yp + 3);
    float4* op = (float4*)out + (size_t)__ldg(dst + e) * 4;
    RED4(op + 0, a0); RED4(op + 1, a1); RED4(op + 2, a2); RED4(op + 3, a3);
}

// ---------------- fused 6-way lin + bias + relu-fold + BN-stats ----------------
// out32[j] = sum_kb sum_i V_kb[i] * W[kb][j][i] + sum_kb b[kb][j]
// h[c] = out32[c] + relu(out32[c+16]); stats: per-column sum & sumsq of h.
__global__ void __launch_bounds__(256) fused_gemm_h(
    const float* __restrict__ in0, const float* __restrict__ deg,
    const float* __restrict__ agg, const float* __restrict__ z1p,
    const float* __restrict__ z2p, const float* __restrict__ z4p,
    const float* __restrict__ W, const float* __restrict__ Bv,
    float* __restrict__ hout, int statsel, int nrows)
{
    __shared__ float ws[96 * 32];
    __shared__ float bsum[32];
    __shared__ float redbuf[8 * 32];

    for (int t = threadIdx.x; t < 96 * 32; t += 256) {
        int k = t >> 9;
        int rem = t & 511;
        int j = rem >> 4;
        int i = rem & 15;
        ws[(k * 16 + i) * 32 + j] = W[t];
    }
    if (threadIdx.x < 32) {
        float s = 0.f;
        #pragma unroll
        for (int k = 0; k < 6; k++) s += Bv[k * 32 + threadIdx.x];
        bsum[threadIdx.x] = s;
    }
    __syncthreads();

    int r = blockIdx.x * 256 + threadIdx.x;
    float h[16];
    #pragma unroll
    for (int c = 0; c < 16; c++) h[c] = 0.f;

    if (r < nrows) {
        float acc[32];
        #pragma unroll
        for (int j = 0; j < 32; j++) acc[j] = bsum[j];
        size_t r4 = (size_t)r * 4;
        const float4* srcs[6];
        srcs[0] = (const float4*)in0 + r4;
        srcs[1] = srcs[0];
        srcs[2] = (const float4*)agg + r4;
        srcs[3] = (const float4*)z1p + r4;
        srcs[4] = (const float4*)z2p + r4;
        srcs[5] = (const float4*)z4p + r4;
        float dg = __ldg(deg + r);
        #pragma unroll 1
        for (int kb = 0; kb < 6; kb++) {
            float4 a0 = __ldg(srcs[kb] + 0);
            float4 a1 = __ldg(srcs[kb] + 1);
            float4 a2 = __ldg(srcs[kb] + 2);
            float4 a3 = __ldg(srcs[kb] + 3);
            float v[16] = {a0.x, a0.y, a0.z, a0.w, a1.x, a1.y, a1.z, a1.w,
                           a2.x, a2.y, a2.z, a2.w, a3.x, a3.y, a3.z, a3.w};
            if (kb == 1) {
                #pragma unroll
                for (int i = 0; i < 16; i++) v[i] *= dg;
            }
            const float* wp = &ws[kb * 16 * 32];
            #pragma unroll
            for (int i = 0; i < 16; i++) {
                float vi = v[i];
                #pragma unroll
                for (int j = 0; j < 32; j++)
                    acc[j] = fmaf(vi, wp[i * 32 + j], acc[j]);
            }
        }
        #pragma unroll
        for (int c = 0; c < 16; c++)
            h[c] = acc[c] + fmaxf(acc[c + 16], 0.f);
        float4* ho = (float4*)hout + r4;
        ho[0] = make_float4(h[0],  h[1],  h[2],  h[3]);
        ho[1] = make_float4(h[4],  h[5],  h[6],  h[7]);
        ho[2] = make_float4(h[8],  h[9],  h[10], h[11]);
        ho[3] = make_float4(h[12], h[13], h[14], h[15]);
    }

    // per-column sum / sumsq reduction
    int lane = threadIdx.x & 31;
    int warp = threadIdx.x >> 5;
    #pragma unroll
    for (int c = 0; c < 16; c++) {
        float a = h[c];
        float b = a * a;
        #pragma unroll
        for (int o = 16; o > 0; o >>= 1) {
            a += __shfl_xor_sync(0xFFFFFFFFu, a, o);
            b += __shfl_xor_sync(0xFFFFFFFFu, b, o);
        }
        if (lane == 0) {
            redbuf[warp * 32 + c]      = a;
            redbuf[warp * 32 + 16 + c] = b;
        }
    }
    __syncthreads();
    if (threadIdx.x < 32) {
        float s = 0.f;
        #pragma unroll
        for (int w = 0; w < 8; w++) s += redbuf[w * 32 + threadIdx.x];
        atomicAdd(&g_stats[statsel * 32 + threadIdx.x], s);
    }
}

// ---------------- BN finalize + apply ----------------
__global__ void bn_finalize(
    const float* __restrict__ wx, const float* __restrict__ bx,
    const float* __restrict__ wy, const float* __restrict__ by,
    int N, int E)
{
    int t = threadIdx.x;
    if (t >= 32) return;
    int sel = t >> 4;
    int c = t & 15;
    float cnt = sel ? (float)E : (float)N;
    float m   = g_stats[sel * 32 + c] / cnt;
    float var = g_stats[sel * 32 + 16 + c] / cnt - m * m;
    const float* w = sel ? wy : wx;
    const float* b = sel ? by : bx;
    float scale = rsqrtf(var + 1e-5f) * __ldg(w + c);
    g_bn[sel * 32 + c]      = scale;
    g_bn[sel * 32 + 16 + c] = __ldg(b + c) - m * scale;
}

__global__ void __launch_bounds__(256) bn_apply(float* __restrict__ h, int nrows, int bnoff) {
    long long i = (long long)blockIdx.x * blockDim.x + threadIdx.x;  // float4 index
    long long tot = (long long)nrows * 4;
    if (i >= tot) return;
    int c = ((int)(i & 3)) * 4;
    const float* bn = g_bn + bnoff;
    float4 v = ((float4*)h)[i];
    v.x = v.x * bn[c + 0] + bn[16 + c + 0];
    v.y = v.y * bn[c + 1] + bn[16 + c + 1];
    v.z = v.z * bn[c + 2] + bn[16 + c + 2];
    v.w = v.w * bn[c + 3] + bn[16 + c + 3];
    ((float4*)h)[i] = v;
}

// ---------------- host ----------------
static void* sym_addr(const void* s) {
    void* p = nullptr;
    cudaGetSymbolAddress(&p, s);
    return p;
}

extern "C" void kernel_launch(void* const* d_in, const int* in_sizes, int n_in,
                              void* d_out, int out_size)
{
    const float* x       = (const float*)d_in[0];
    const float* y       = (const float*)d_in[1];
    const float* deg_g   = (const float*)d_in[2];
    const float* deg_lg  = (const float*)d_in[3];
    const float* theta_W = (const float*)d_in[4];
    const float* theta_b = (const float*)d_in[5];
    const float* gamma_W = (const float*)d_in[6];
    const float* gamma_b = (const float*)d_in[7];
    const float* bn_x_w  = (const float*)d_in[8];
    const float* bn_x_b  = (const float*)d_in[9];
    const float* bn_y_w  = (const float*)d_in[10];
    const float* bn_y_b  = (const float*)d_in[11];
    const int* src_g     = (const int*)d_in[12];
    const int* dst_g     = (const int*)d_in[13];
    const int* src_lg    = (const int*)d_in[14];
    const int* dst_lg    = (const int*)d_in[15];
    const int* eid2nid   = (const int*)d_in[16];

    int N  = in_sizes[0] / 16;
    int E  = in_sizes[1] / 16;
    int EL = in_sizes[14];

    float* out_x = (float*)d_out;
    float* out_y = out_x + (size_t)N * 16;

    float* ze1   = (float*)sym_addr(g_ze1);
    float* ze2   = (float*)sym_addr(g_ze2);
    float* zet   = (float*)sym_addr(g_zet);
    float* ze4   = (float*)sym_addr(g_ze4);
    float* xyagg = (float*)sym_addr(g_xyagg);
    float* zn1   = (float*)sym_addr(g_zn1);
    float* zn2   = (float*)sym_addr(g_zn2);
    float* znt   = (float*)sym_addr(g_znt);
    float* zn4   = (float*)sym_addr(g_zn4);
    float* yx    = (float*)sym_addr(g_yx);

    int e4 = E * 4, n4 = N * 4;

    // 1) zero accumulators + stats
    zero_all<<<cdiv_u(e4 > n4 ? e4 : n4, 256), 256>>>(e4, n4);

    // 2) line-graph: ze1 = A_lg y, xyagg = A_lg x[eid2nid] (fused pass)
    lg_pass1<<<cdiv_u(EL, 256), 256>>>(y, x, src_lg, dst_lg, eid2nid, ze1, xyagg, EL);

    // 3) chained line-graph aggregates: ze2 = A ze1, zet = A ze2, ze4 = A zet
    spmm16<<<cdiv_u(EL, 256), 256>>>(ze1, src_lg, dst_lg, ze2, EL);
    spmm16<<<cdiv_u(EL, 256), 256>>>(ze2, src_lg, dst_lg, zet, EL);
    spmm16<<<cdiv_u(EL, 256), 256>>>(zet, src_lg, dst_lg, ze4, EL);

    // 4) node graph aggregates
    spmm16<<<cdiv_u(E, 256), 256>>>(x,   src_g, dst_g, zn1, E);
    spmm16<<<cdiv_u(E, 256), 256>>>(zn1, src_g, dst_g, zn2, E);
    spmm16<<<cdiv_u(E, 256), 256>>>(zn2, src_g, dst_g, znt, E);
    spmm16<<<cdiv_u(E, 256), 256>>>(znt, src_g, dst_g, zn4, E);

    // 5) yx = segment_sum(y by dst_g)
    yx_kernel<<<cdiv_u(E, 256), 256>>>(y, dst_g, yx, E);

    // 6) fused 6-way lin + relu-fold + BN stats (writes h into d_out regions)
    fused_gemm_h<<<cdiv_u(N, 256), 256>>>(x, deg_g, yx, zn1, zn2, zn4,
                                          theta_W, theta_b, out_x, 0, N);
    fused_gemm_h<<<cdiv_u(E, 256), 256>>>(y, deg_lg, xyagg, ze1, ze2, ze4,
                                          gamma_W, gamma_b, out_y, 1, E);

    // 7) BN finalize + in-place normalize
    bn_finalize<<<1, 32>>>(bn_x_w, bn_x_b, bn_y_w, bn_y_b, N, E);
    bn_apply<<<cdiv_u((long long)N * 4, 256), 256>>>(out_x, N, 0);
    bn_apply<<<cdiv_u((long long)E * 4, 256), 256>>>(out_y, E, 32);

    (void)n_in; (void)out_size;
}

// round 2
// speedup vs baseline: 1.9214x; 1.9214x over previous
#include <cuda_runtime.h>
#include <cstdint>

#define N_MAX   100000
#define E_MAX   1600000
#define EL_MAX  6400000

// ---------------- scratch (device globals; no dynamic allocation) ----------------
__device__ float g_ze1[E_MAX * 16];
__device__ float g_ze2[E_MAX * 16];
__device__ float g_zet[E_MAX * 16];
__device__ float g_ze4[E_MAX * 16];
__device__ float g_xyagg[E_MAX * 16];
__device__ float g_zn1[N_MAX * 16];
__device__ float g_zn2[N_MAX * 16];
__device__ float g_znt[N_MAX * 16];
__device__ float g_zn4[N_MAX * 16];
__device__ float g_yx[N_MAX * 16];

__device__ int g_tmp_lg[E_MAX];        // counts, then cursors
__device__ int g_off_lg[E_MAX + 1];
__device__ int g_csr_lg[EL_MAX];
__device__ int g_tmp_g[N_MAX];
__device__ int g_off_g[N_MAX + 1];
__device__ int g_csr_g_src[E_MAX];
__device__ int g_csr_g_eid[E_MAX];
__device__ int g_bsums_lg[2048];
__device__ int g_bsums_g[256];

__device__ float g_stats[64];
__device__ float g_bn[64];

static inline unsigned cdiv_u(long long a, long long b) { return (unsigned)((a + b - 1) / b); }

// ---------------- f32x2 helpers ----------------
__device__ __forceinline__ unsigned long long pk2(float a, float b) {
    unsigned long long r;
    asm("mov.b64 %0, {%1, %2};" : "=l"(r) : "r"(__float_as_uint(a)), "r"(__float_as_uint(b)));
    return r;
}
__device__ __forceinline__ unsigned long long fma2(
    unsigned long long a, unsigned long long b, unsigned long long c) {
    unsigned long long d;
    asm("fma.rn.f32x2 %0, %1, %2, %3;" : "=l"(d) : "l"(a), "l"(b), "l"(c));
    return d;
}
__device__ __forceinline__ void up2(unsigned long long v, float& lo, float& hi) {
    unsigned int a, b;
    asm("mov.b64 {%0, %1}, %2;" : "=r"(a), "=r"(b) : "l"(v));
    lo = __uint_as_float(a); hi = __uint_as_float(b);
}

// ---------------- small zero-init (counts + stats only) ----------------
__global__ void zero_small(int nE, int nN) {
    int i = blockIdx.x * blockDim.x + threadIdx.x;
    if (i < nE) g_tmp_lg[i] = 0;
    if (i < nN) g_tmp_g[i] = 0;
    if (i < 64) g_stats[i] = 0.f;
}

// ---------------- CSR build ----------------
__global__ void __launch_bounds__(256) hist_k(const int* __restrict__ dst, int* __restrict__ cnt, int n) {
    int e = blockIdx.x * blockDim.x + threadIdx.x;
    if (e < n) atomicAdd(cnt + __ldg(dst + e), 1);
}

// block-level exclusive scan: 256 threads x 4 elems = 1024/block
__global__ void __launch_bounds__(256) scan_blocks(
    const int* __restrict__ cnt, int* __restrict__ off, int* __restrict__ bsums, int n)
{
    __shared__ int warpsum[8];
    int t = threadIdx.x;
    int i0 = blockIdx.x * 1024 + t * 4;
    int4 v = make_int4(0, 0, 0, 0);
    if (i0 + 3 < n) v = *(const int4*)(cnt + i0);
    else {
        if (i0 < n)     v.x = cnt[i0];
        if (i0 + 1 < n) v.y = cnt[i0 + 1];
        if (i0 + 2 < n) v.z = cnt[i0 + 2];
    }
    int s = v.x + v.y + v.z + v.w;
    int lane = t & 31, w = t >> 5;
    int incl = s;
    #pragma unroll
    for (int o = 1; o < 32; o <<= 1) {
        int nv = __shfl_up_sync(0xFFFFFFFFu, incl, o);
        if (lane >= o) incl += nv;
    }
    if (lane == 31) warpsum[w] = incl;
    __syncthreads();
    if (t < 8) {
        int ws = warpsum[t];
        int in2 = ws;
        #pragma unroll
        for (int o = 1; o < 8; o <<= 1) {
            int nv = __shfl_up_sync(0x000000FFu, in2, o);
            if (t >= o) in2 += nv;
        }
        warpsum[t] = in2 - ws;  // exclusive
    }
    __syncthreads();
    int excl = warpsum[w] + incl - s;
    if (i0 < n) {
        int a = excl;
        off[i0] = a; a += v.x;
        if (i0 + 1 < n) off[i0 + 1] = a; a += v.y;
        if (i0 + 2 < n) off[i0 + 2] = a; a += v.z;
        if (i0 + 3 < n) off[i0 + 3] = a;
    }
    if (t == 255) bsums[blockIdx.x] = excl + s;  // block total
}

// single-block scan of block sums (nb <= 2048)
__global__ void __launch_bounds__(1024) scan_bsums(int* __restrict__ bsums, int nb) {
    __shared__ int wsum[32];
    int t = threadIdx.x;
    int k = (nb + 1023) >> 10;
    int i0 = t * k;
    int s = 0;
    for (int q = 0; q < k; q++) { int i = i0 + q; if (i < nb) s += bsums[i]; }
    int lane = t & 31, w = t >> 5;
    int incl = s;
    #pragma unroll
    for (int o = 1; o < 32; o <<= 1) {
        int nv = __shfl_up_sync(0xFFFFFFFFu, incl, o);
        if (lane >= o) incl += nv;
    }
    if (lane == 31) wsum[w] = incl;
    __syncthreads();
    if (t < 32) {
        int ws = wsum[t];
        int in2 = ws;
        #pragma unroll
        for (int o = 1; o < 32; o <<= 1) {
            int nv = __shfl_up_sync(0xFFFFFFFFu, in2, o);
            if (t >= o) in2 += nv;
        }
        wsum[t] = in2 - ws;
    }
    __syncthreads();
    int excl = wsum[w] + incl - s;
    for (int q = 0; q < k; q++) {
        int i = i0 + q;
        if (i < nb) { int v = bsums[i]; bsums[i] = excl; excl += v; }
    }
}

__global__ void __launch_bounds__(256) add_offsets(
    int* __restrict__ off, int* __restrict__ cur, const int* __restrict__ bsums,
    int n, int total)
{
    int i = blockIdx.x * 256 + threadIdx.x;
    if (i < n) {
        int v = off[i] + __ldg(bsums + (i >> 10));
        off[i] = v;
        cur[i] = v;
    }
    if (i == 0) off[n] = total;
}

__global__ void __launch_bounds__(256) scatter_lg_k(
    const int* __restrict__ src, const int* __restrict__ dst,
    int* __restrict__ cur, int* __restrict__ csr, int n)
{
    int e = blockIdx.x * blockDim.x + threadIdx.x;
    if (e >= n) return;
    int p = atomicAdd(cur + __ldg(dst + e), 1);
    csr[p] = __ldg(src + e);
}

__global__ void __launch_bounds__(256) scatter_g_k(
    const int* __restrict__ src, const int* __restrict__ dst,
    int* __restrict__ cur, int* __restrict__ csrs, int* __restrict__ csre, int n)
{
    int e = blockIdx.x * blockDim.x + threadIdx.x;
    if (e >= n) return;
    int p = atomicAdd(cur + __ldg(dst + e), 1);
    csrs[p] = __ldg(src + e);
    csre[p] = e;
}

// ---------------- gather-based segment sums ----------------
// thread t: dst row d = t>>2, float4 chunk c = t&3
__global__ void __launch_bounds__(256) spmm_gather(
    const float* __restrict__ z, const int* __restrict__ off,
    const int* __restrict__ csr, float* __restrict__ out, int ndst)
{
    int t = blockIdx.x * blockDim.x + threadIdx.x;
    int d = t >> 2, c = t & 3;
    if (d >= ndst) return;
    int k0 = __ldg(off + d), k1 = __ldg(off + d + 1);
    float4 acc = make_float4(0.f, 0.f, 0.f, 0.f);
    for (int k = k0; k < k1; k++) {
        int s = __ldg(csr + k);
        float4 v = __ldg((const float4*)z + (size_t)s * 4 + c);
        acc.x += v.x; acc.y += v.y; acc.z += v.z; acc.w += v.w;
    }
    ((float4*)out)[(size_t)d * 4 + c] = acc;
}

// lg pass1: ze1[d] = sum y[s];  xyagg[d] = sum x[e2n[s]]
__global__ void __launch_bounds__(256) lg_pass1_gather(
    const float* __restrict__ y, const float* __restrict__ x,
    const int* __restrict__ e2n, const int* __restrict__ off,
    const int* __restrict__ csr,
    float* __restrict__ ze1, float* __restrict__ xyagg, int ndst)
{
    int t = blockIdx.x * blockDim.x + threadIdx.x;
    int d = t >> 2, c = t & 3;
    if (d >= ndst) return;
    int k0 = __ldg(off + d), k1 = __ldg(off + d + 1);
    float4 ay = make_float4(0.f, 0.f, 0.f, 0.f);
    float4 ax = make_float4(0.f, 0.f, 0.f, 0.f);
    for (int k = k0; k < k1; k++) {
        int s = __ldg(csr + k);
        float4 v = __ldg((const float4*)y + (size_t)s * 4 + c);
        ay.x += v.x; ay.y += v.y; ay.z += v.z; ay.w += v.w;
        int nid = __ldg(e2n + s);
        float4 w = __ldg((const float4*)x + (size_t)nid * 4 + c);
        ax.x += w.x; ax.y += w.y; ax.z += w.z; ax.w += w.w;
    }
    ((float4*)ze1)[(size_t)d * 4 + c] = ay;
    ((float4*)xyagg)[(size_t)d * 4 + c] = ax;
}

// g pass1: zn1[d] = sum x[src];  yx[d] = sum y[eid]
__global__ void __launch_bounds__(256) g_pass1_gather(
    const float* __restrict__ x, const float* __restrict__ y,
    const int* __restrict__ off, const int* __restrict__ csrs,
    const int* __restrict__ csre,
    float* __restrict__ zn1, float* __restrict__ yx, int ndst)
{
    int t = blockIdx.x * blockDim.x + threadIdx.x;
    int d = t >> 2, c = t & 3;
    if (d >= ndst) return;
    int k0 = __ldg(off + d), k1 = __ldg(off + d + 1);
    float4 ax = make_float4(0.f, 0.f, 0.f, 0.f);
    float4 ay = make_float4(0.f, 0.f, 0.f, 0.f);
    for (int k = k0; k < k1; k++) {
        int s = __ldg(csrs + k);
        int e = __ldg(csre + k);
        float4 v = __ldg((const float4*)x + (size_t)s * 4 + c);
        ax.x += v.x; ax.y += v.y; ax.z += v.z; ax.w += v.w;
        float4 w = __ldg((const float4*)y + (size_t)e * 4 + c);
        ay.x += w.x; ay.y += w.y; ay.z += w.z; ay.w += w.w;
    }
    ((float4*)zn1)[(size_t)d * 4 + c] = ax;
    ((float4*)yx)[(size_t)d * 4 + c] = ay;
}

// ---------------- fused 6-way lin + relu-fold + BN stats (f32x2, 2 rows/thread) ----
__global__ void __launch_bounds__(256) fused_gemm2(
    const float* __restrict__ in0, const float* __restrict__ deg,
    const float* __restrict__ agg, const float* __restrict__ z1p,
    const float* __restrict__ z2p, const float* __restrict__ z4p,
    const float* __restrict__ W, const float* __restrict__ Bv,
    float* __restrict__ hout, int statsel, int nrows)
{
    __shared__ float ws[96 * 32];
    __shared__ unsigned long long bs2[16];
    __shared__ float redbuf[8 * 32];

    for (int t = threadIdx.x; t < 96 * 32; t += 256) {
        int kb = t >> 9;
        int rem = t & 511;
        int j = rem >> 4;
        int i = rem & 15;
        ws[(kb * 16 + i) * 32 + j] = W[t];
    }
    if (threadIdx.x < 16) {
        float lo = 0.f, hi = 0.f;
        #pragma unroll
        for (int kb = 0; kb < 6; kb++) {
            lo += Bv[kb * 32 + 2 * threadIdx.x];
            hi += Bv[kb * 32 + 2 * threadIdx.x + 1];
        }
        bs2[threadIdx.x] = pk2(lo, hi);
    }
    __syncthreads();

    int r0 = blockIdx.x * 512 + threadIdx.x;
    int r1 = r0 + 256;
    bool ok0 = r0 < nrows, ok1 = r1 < nrows;

    unsigned long long acc0[16], acc1[16];
    #pragma unroll
    for (int q = 0; q < 16; q++) { acc0[q] = bs2[q]; acc1[q] = bs2[q]; }

    float v0[16], v1[16];
    #pragma unroll
    for (int q = 0; q < 16; q++) { v0[q] = 0.f; v1[q] = 0.f; }
    float dg0 = ok0 ? __ldg(deg + r0) : 0.f;
    float dg1 = ok1 ? __ldg(deg + r1) : 0.f;

    #pragma unroll 1
    for (int kb = 0; kb < 6; kb++) {
        const float* sp = (kb <= 1) ? in0 : (kb == 2) ? agg : (kb == 3) ? z1p
                        : (kb == 4) ? z2p : z4p;
        if (ok0) {
            const float4* p = (const float4*)sp + (size_t)r0 * 4;
            float4 a = __ldg(p), b = __ldg(p + 1), c = __ldg(p + 2), d = __ldg(p + 3);
            v0[0]=a.x; v0[1]=a.y; v0[2]=a.z; v0[3]=a.w;
            v0[4]=b.x; v0[5]=b.y; v0[6]=b.z; v0[7]=b.w;
            v0[8]=c.x; v0[9]=c.y; v0[10]=c.z; v0[11]=c.w;
            v0[12]=d.x; v0[13]=d.y; v0[14]=d.z; v0[15]=d.w;
        }
        if (ok1) {
            const float4* p = (const float4*)sp + (size_t)r1 * 4;
            float4 a = __ldg(p), b = __ldg(p + 1), c = __ldg(p + 2), d = __ldg(p + 3);
            v1[0]=a.x; v1[1]=a.y; v1[2]=a.z; v1[3]=a.w;
            v1[4]=b.x; v1[5]=b.y; v1[6]=b.z; v1[7]=b.w;
            v1[8]=c.x; v1[9]=c.y; v1[10]=c.z; v1[11]=c.w;
            v1[12]=d.x; v1[13]=d.y; v1[14]=d.z; v1[15]=d.w;
        }
        if (kb == 1) {
            #pragma unroll
            for (int q = 0; q < 16; q++) { v0[q] *= dg0; v1[q] *= dg1; }
        }
        #pragma unroll
        for (int i = 0; i < 16; i++) {
            unsigned long long vd0 = pk2(v0[i], v0[i]);
            unsigned long long vd1 = pk2(v1[i], v1[i]);
            const ulonglong2* wp2 = (const ulonglong2*)&ws[(kb * 16 + i) * 32];
            #pragma unroll
            for (int q2 = 0; q2 < 8; q2++) {
                ulonglong2 ww = wp2[q2];
                acc0[2*q2]   = fma2(vd0, ww.x, acc0[2*q2]);
                acc0[2*q2+1] = fma2(vd0, ww.y, acc0[2*q2+1]);
                acc1[2*q2]   = fma2(vd1, ww.x, acc1[2*q2]);
                acc1[2*q2+1] = fma2(vd1, ww.y, acc1[2*q2+1]);
            }
        }
    }

    // epilogue: h[c] = out[c] + relu(out[c+16]); accumulate per-column stats
    float hs[16], hq[16];
    #pragma unroll
    for (int c = 0; c < 16; c++) { hs[c] = 0.f; hq[c] = 0.f; }

    if (ok0) {
        float h[16];
        #pragma unroll
        for (int q = 0; q < 8; q++) {
            float a0, a1, b0, b1;
            up2(acc0[q], a0, a1);
            up2(acc0[8 + q], b0, b1);
            h[2*q]   = a0 + fmaxf(b0, 0.f);
            h[2*q+1] = a1 + fmaxf(b1, 0.f);
        }
        float4* ho = (float4*)hout + (size_t)r0 * 4;
        ho[0] = make_float4(h[0], h[1], h[2], h[3]);
        ho[1] = make_float4(h[4], h[5], h[6], h[7]);
        ho[2] = make_float4(h[8], h[9], h[10], h[11]);
        ho[3] = make_float4(h[12], h[13], h[14], h[15]);
        #pragma unroll
        for (int c = 0; c < 16; c++) { hs[c] += h[c]; hq[c] += h[c] * h[c]; }
    }
    if (ok1) {
        float h[16];
        #pragma unroll
        for (int q = 0; q < 8; q++) {
            float a0, a1, b0, b1;
            up2(acc1[q], a0, a1);
            up2(acc1[8 + q], b0, b1);
            h[2*q]   = a0 + fmaxf(b0, 0.f);
            h[2*q+1] = a1 + fmaxf(b1, 0.f);
        }
        float4* ho = (float4*)hout + (size_t)r1 * 4;
        ho[0] = make_float4(h[0], h[1], h[2], h[3]);
        ho[1] = make_float4(h[4], h[5], h[6], h[7]);
        ho[2] = make_float4(h[8], h[9], h[10], h[11]);
        ho[3] = make_float4(h[12], h[13], h[14], h[15]);
        #pragma unroll
        for (int c = 0; c < 16; c++) { hs[c] += h[c]; hq[c] += h[c] * h[c]; }
    }

    int lane = threadIdx.x & 31;
    int warp = threadIdx.x >> 5;
    #pragma unroll
    for (int c = 0; c < 16; c++) {
        float a = hs[c];
        float b = hq[c];
        #pragma unroll
        for (int o = 16; o > 0; o >>= 1) {
            a += __shfl_xor_sync(0xFFFFFFFFu, a, o);
            b += __shfl_xor_sync(0xFFFFFFFFu, b, o);
        }
        if (lane == 0) {
            redbuf[warp * 32 + c]      = a;
            redbuf[warp * 32 + 16 + c] = b;
        }
    }
    __syncthreads();
    if (threadIdx.x < 32) {
        float s = 0.f;
        #pragma unroll
        for (int w = 0; w < 8; w++) s += redbuf[w * 32 + threadIdx.x];
        atomicAdd(&g_stats[statsel * 32 + threadIdx.x], s);
    }
}

// ---------------- BN finalize + apply ----------------
__global__ void bn_finalize(
    const float* __restrict__ wx, const float* __restrict__ bx,
    const float* __restrict__ wy, const float* __restrict__ by,
    int N, int E)
{
    int t = threadIdx.x;
    if (t >= 32) return;
    int sel = t >> 4;
    int c = t & 15;
    float cnt = sel ? (float)E : (float)N;
    float m   = g_stats[sel * 32 + c] / cnt;
    float var = g_stats[sel * 32 + 16 + c] / cnt - m * m;
    const float* w = sel ? wy : wx;
    const float* b = sel ? by : bx;
    float scale = rsqrtf(var + 1e-5f) * __ldg(w + c);
    g_bn[sel * 32 + c]      = scale;
    g_bn[sel * 32 + 16 + c] = __ldg(b + c) - m * scale;
}

__global__ void __launch_bounds__(256) bn_apply(float* __restrict__ h, int nrows, int bnoff) {
    long long i = (long long)blockIdx.x * blockDim.x + threadIdx.x;  // float4 index
    long long tot = (long long)nrows * 4;
    if (i >= tot) return;
    int c = ((int)(i & 3)) * 4;
    const float* bn = g_bn + bnoff;
    float4 v = ((float4*)h)[i];
    v.x = v.x * bn[c + 0] + bn[16 + c + 0];
    v.y = v.y * bn[c + 1] + bn[16 + c + 1];
    v.z = v.z * bn[c + 2] + bn[16 + c + 2];
    v.w = v.w * bn[c + 3] + bn[16 + c + 3];
    ((float4*)h)[i] = v;
}

// ---------------- host ----------------
static void* sym_addr(const void* s) {
    void* p = nullptr;
    cudaGetSymbolAddress(&p, s);
    return p;
}

extern "C" void kernel_launch(void* const* d_in, const int* in_sizes, int n_in,
                              void* d_out, int out_size)
{
    const float* x       = (const float*)d_in[0];
    const float* y       = (const float*)d_in[1];
    const float* deg_g   = (const float*)d_in[2];
    const float* deg_lg  = (const float*)d_in[3];
    const float* theta_W = (const float*)d_in[4];
    const float* theta_b = (const float*)d_in[5];
    const float* gamma_W = (const float*)d_in[6];
    const float* gamma_b = (const float*)d_in[7];
    const float* bn_x_w  = (const float*)d_in[8];
    const float* bn_x_b  = (const float*)d_in[9];
    const float* bn_y_w  = (const float*)d_in[10];
    const float* bn_y_b  = (const float*)d_in[11];
    const int* src_g     = (const int*)d_in[12];
    const int* dst_g     = (const int*)d_in[13];
    const int* src_lg    = (const int*)d_in[14];
    const int* dst_lg    = (const int*)d_in[15];
    const int* eid2nid   = (const int*)d_in[16];

    int N  = in_sizes[0] / 16;
    int E  = in_sizes[1] / 16;
    int EL = in_sizes[14];

    float* out_x = (float*)d_out;
    float* out_y = out_x + (size_t)N * 16;

    float* ze1   = (float*)sym_addr(g_ze1);
    float* ze2   = (float*)sym_addr(g_ze2);
    float* zet   = (float*)sym_addr(g_zet);
    float* ze4   = (float*)sym_addr(g_ze4);
    float* xyagg = (float*)sym_addr(g_xyagg);
    float* zn1   = (float*)sym_addr(g_zn1);
    float* zn2   = (float*)sym_addr(g_zn2);
    float* znt   = (float*)sym_addr(g_znt);
    float* zn4   = (float*)sym_addr(g_zn4);
    float* yx    = (float*)sym_addr(g_yx);

    int* tmp_lg = (int*)sym_addr(g_tmp_lg);
    int* off_lg = (int*)sym_addr(g_off_lg);
    int* csr_lg = (int*)sym_addr(g_csr_lg);
    int* tmp_g  = (int*)sym_addr(g_tmp_g);
    int* off_g  = (int*)sym_addr(g_off_g);
    int* csr_gs = (int*)sym_addr(g_csr_g_src);
    int* csr_ge = (int*)sym_addr(g_csr_g_eid);
    int* bs_lg  = (int*)sym_addr(g_bsums_lg);
    int* bs_g   = (int*)sym_addr(g_bsums_g);

    // 1) zero counts + stats
    zero_small<<<cdiv_u(E > N ? E : N, 256), 256>>>(E, N);

    // 2) CSR build (dst-sorted) for both graphs
    hist_k<<<cdiv_u(EL, 256), 256>>>(dst_lg, tmp_lg, EL);
    hist_k<<<cdiv_u(E, 256), 256>>>(dst_g, tmp_g, E);

    int nb_lg = cdiv_u(E, 1024);
    scan_blocks<<<nb_lg, 256>>>(tmp_lg, off_lg, bs_lg, E);
    scan_bsums<<<1, 1024>>>(bs_lg, nb_lg);
    add_offsets<<<cdiv_u(E, 256), 256>>>(off_lg, tmp_lg, bs_lg, E, EL);

    int nb_g = cdiv_u(N, 1024);
    scan_blocks<<<nb_g, 256>>>(tmp_g, off_g, bs_g, N);
    scan_bsums<<<1, 1024>>>(bs_g, nb_g);
    add_offsets<<<cdiv_u(N, 256), 256>>>(off_g, tmp_g, bs_g, N, E);

    scatter_lg_k<<<cdiv_u(EL, 256), 256>>>(src_lg, dst_lg, tmp_lg, csr_lg, EL);
    scatter_g_k<<<cdiv_u(E, 256), 256>>>(src_g, dst_g, tmp_g, csr_gs, csr_ge, E);

    // 3) line-graph gathers: ze1 = A y (+ xyagg = A x[e2n]), then chained
    unsigned gl = cdiv_u((long long)E * 4, 256);
    lg_pass1_gather<<<gl, 256>>>(y, x, eid2nid, off_lg, csr_lg, ze1, xyagg, E);
    spmm_gather<<<gl, 256>>>(ze1, off_lg, csr_lg, ze2, E);
    spmm_gather<<<gl, 256>>>(ze2, off_lg, csr_lg, zet, E);
    spmm_gather<<<gl, 256>>>(zet, off_lg, csr_lg, ze4, E);

    // 4) node-graph gathers: zn1 = A x (+ yx = sum y), then chained
    unsigned gn = cdiv_u((long long)N * 4, 256);
    g_pass1_gather<<<gn, 256>>>(x, y, off_g, csr_gs, csr_ge, zn1, yx, N);
    spmm_gather<<<gn, 256>>>(zn1, off_g, csr_gs, zn2, N);
    spmm_gather<<<gn, 256>>>(zn2, off_g, csr_gs, znt, N);
    spmm_gather<<<gn, 256>>>(znt, off_g, csr_gs, zn4, N);

    // 5) fused 6-way lin + relu-fold + BN stats
    fused_gemm2<<<cdiv_u(N, 512), 256>>>(x, deg_g, yx, zn1, zn2, zn4,
                                         theta_W, theta_b, out_x, 0, N);
    fused_gemm2<<<cdiv_u(E, 512), 256>>>(y, deg_lg, xyagg, ze1, ze2, ze4,
                                         gamma_W, gamma_b, out_y, 1, E);

    // 6) BN finalize + in-place normalize
    bn_finalize<<<1, 32>>>(bn_x_w, bn_x_b, bn_y_w, bn_y_b, N, E);
    bn_apply<<<cdiv_u((long long)N * 4, 256), 256>>>(out_x, N, 0);
    bn_apply<<<cdiv_u((long long)E * 4, 256), 256>>>(out_y, E, 32);

    (void)n_in; (void)out_size;
}